// round 16
// baseline (speedup 1.0000x reference)
#include <cuda_runtime.h>
#include <cuda_fp16.h>
#include <cstdint>

// (s, b, h, d) = (2048, 2, 16, 128), fp32 in/out, causal, scale = 1/sqrt(128)
#define SLEN     2048
#define NB       2
#define NH       16
#define HD       128
#define RSTRIDE  4096            // floats between sequence rows
#define BM       64
#define BN       32
#define QTILES   (SLEN/BM)       // 32
#define NTHREADS 128
#define SCALE    0.08838834764831845f
#define LOG2E    1.4426950408889634f
#define NELEM    (SLEN*NB*NH*HD) // 8388608

typedef unsigned int uint32;

// ---- fp16 copies of K, V (same [s][b][h][d] layout) ----
__device__ __align__(256) __half g_k16[NELEM];
__device__ __align__(256) __half g_v16[NELEM];

// ---- smem: 3 KV stages x 16KB; rows 256B (128 f16), 16B chunks XOR-swizzled ----
#define STAGE_B  16384
#define BUF_V    8192            // V tile after K tile inside a stage
#define SMEM_TOTAL (3 * STAGE_B)   // 49152 -> 3 CTAs/SM
// Q (f16, pre-scaled by SCALE*log2e) staged transiently in stage 0

// ---------------- helpers ----------------
__device__ __forceinline__ uint32 smem_u32_of(const void* p) {
    uint32 a;
    asm("{ .reg .u64 t; cvta.to.shared.u64 t, %1; cvt.u32.u64 %0, t; }" : "=r"(a) : "l"(p));
    return a;
}
__device__ __forceinline__ uint32 pk_h2(float x, float y) {
    __half2 h = __floats2half2_rn(x, y);
    return *reinterpret_cast<uint32*>(&h);
}
__device__ __forceinline__ float ex2(float x) {    // exp2, single MUFU op
    float r;
    asm("ex2.approx.f32 %0, %1;" : "=f"(r) : "f"(x));
    return r;
}
__device__ __forceinline__ void ldm_x4(uint32 r[4], uint32 addr) {
    asm volatile("ldmatrix.sync.aligned.m8n8.x4.shared.b16 {%0,%1,%2,%3}, [%4];"
                 : "=r"(r[0]), "=r"(r[1]), "=r"(r[2]), "=r"(r[3]) : "r"(addr) : "memory");
}
__device__ __forceinline__ void ldm_x4_t(uint32 r[4], uint32 addr) {
    asm volatile("ldmatrix.sync.aligned.m8n8.x4.trans.shared.b16 {%0,%1,%2,%3}, [%4];"
                 : "=r"(r[0]), "=r"(r[1]), "=r"(r[2]), "=r"(r[3]) : "r"(addr) : "memory");
}
// D += A * B  (m16n8k16, f16 in, f32 accum)
__device__ __forceinline__ void mma_f16(float c[4], const uint32 a[4], uint32 b0, uint32 b1) {
    asm volatile(
        "mma.sync.aligned.m16n8k16.row.col.f32.f16.f16.f32 "
        "{%0,%1,%2,%3}, {%4,%5,%6,%7}, {%8,%9}, {%0,%1,%2,%3};"
        : "+f"(c[0]), "+f"(c[1]), "+f"(c[2]), "+f"(c[3])
        : "r"(a[0]), "r"(a[1]), "r"(a[2]), "r"(a[3]), "r"(b0), "r"(b1));
}
__device__ __forceinline__ void cp16(uint32 dst, const void* src) {
    asm volatile("cp.async.cg.shared.global [%0], [%1], 16;" :: "r"(dst), "l"(src) : "memory");
}
#define CP_COMMIT() asm volatile("cp.async.commit_group;" ::: "memory")
#define CP_WAIT(n)  asm volatile("cp.async.wait_group %0;" :: "n"(n) : "memory")

// ---------------- pre-pass: K,V fp32 -> fp16 (2 groups/thread for MLP) ----------------
__global__ void __launch_bounds__(256)
cvt_kernel(const float4* __restrict__ K, const float4* __restrict__ V)
{
    int i0 = (blockIdx.x * 256 + threadIdx.x) * 2;   // two groups of 8 elements
    float4 ka0 = K[2*i0],   kb0 = K[2*i0+1];
    float4 ka1 = K[2*i0+2], kb1 = K[2*i0+3];
    float4 va0 = V[2*i0],   vb0 = V[2*i0+1];
    float4 va1 = V[2*i0+2], vb1 = V[2*i0+3];
    ((uint4*)g_k16)[i0]   = make_uint4(pk_h2(ka0.x, ka0.y), pk_h2(ka0.z, ka0.w),
                                       pk_h2(kb0.x, kb0.y), pk_h2(kb0.z, kb0.w));
    ((uint4*)g_k16)[i0+1] = make_uint4(pk_h2(ka1.x, ka1.y), pk_h2(ka1.z, ka1.w),
                                       pk_h2(kb1.x, kb1.y), pk_h2(kb1.z, kb1.w));
    ((uint4*)g_v16)[i0]   = make_uint4(pk_h2(va0.x, va0.y), pk_h2(va0.z, va0.w),
                                       pk_h2(vb0.x, vb0.y), pk_h2(vb0.z, vb0.w));
    ((uint4*)g_v16)[i0+1] = make_uint4(pk_h2(va1.x, va1.y), pk_h2(va1.z, va1.w),
                                       pk_h2(vb1.x, vb1.y), pk_h2(vb1.z, vb1.w));
}

// ---------------- main attention kernel (cross-tile pipelined) ----------------
__global__ void __launch_bounds__(NTHREADS, 3)
attn_f16_kernel(const float* __restrict__ Q, float* __restrict__ Out)
{
    extern __shared__ char smem[];
    const uint32 smb = smem_u32_of(smem);

    const int t   = threadIdx.x;
    const int w   = t >> 5;
    const int l   = t & 31;
    const int gid = l >> 2;
    const int tig = l & 3;
    const int rx  = l & 7;

    const int qtile = (int)gridDim.x - 1 - (int)blockIdx.x;   // heavy first
    const int bh    = (int)blockIdx.y;
    const int boff  = (bh >> 4) * (NH * HD) + (bh & 15) * HD;
    const int q0    = qtile * BM;
    const int nk    = 2 * qtile + 2;

    // ---- Q: fp32 load, scale by SCALE*log2e, f16-round, stage, extract ----
    {
        const float qs = SCALE * LOG2E;
        const int qr = t >> 1;
        const float* Qr = Q + (size_t)(q0 + qr) * RSTRIDE + boff;
        #pragma unroll
        for (int i = 0; i < 8; ++i) {
            int ch = (t & 1) + 2 * i;
            const float* p = Qr + ch * 8;
            float4 a = *(const float4*)p;
            float4 b = *(const float4*)(p + 4);
            *(uint4*)(smem + qr * 256 + ((ch ^ (qr & 7)) << 4)) =
                make_uint4(pk_h2(a.x * qs, a.y * qs), pk_h2(a.z * qs, a.w * qs),
                           pk_h2(b.x * qs, b.y * qs), pk_h2(b.z * qs, b.w * qs));
        }
    }
    __syncthreads();

    uint32 qf[8][4];
    {
        const int qrow = w * 16 + (l & 15);
        const int cq0  = l >> 4;
        const uint32 q_row = smb + (uint32)(qrow * 256);
        #pragma unroll
        for (int k = 0; k < 8; ++k)
            ldm_x4(qf[k], q_row + (uint32)(((cq0 + 2 * k) ^ rx) << 4));
    }
    __syncthreads();   // stage0 free for KV(0)

    // KV staging slots
    const int    krow = t >> 2;
    const int    kch0 = t & 3;
    const size_t gsrc = (size_t)krow * RSTRIDE + boff;

    // ---- prologue: issue KV(0)->stage0, KV(1)->stage1 ----
    #pragma unroll
    for (int tt = 0; tt < 2; ++tt) {
        const uint32 nb = smb + (uint32)(tt * STAGE_B);
        const size_t sk = gsrc + (size_t)(tt * BN) * RSTRIDE;
        #pragma unroll
        for (int i = 0; i < 4; ++i) {
            int ch = kch0 + 4 * i;
            const uint32 doff = (uint32)(krow * 256 + ((ch ^ (krow & 7)) << 4));
            cp16(nb + doff,         g_k16 + sk + ch * 8);
            cp16(nb + BUF_V + doff, g_v16 + sk + ch * 8);
        }
        CP_COMMIT();
    }

    // ---- per-lane K/V ldmatrix offsets ----
    const uint32 k_rowoff = (uint32)((((l >> 4) << 3) + (l & 7)) * 256);
    const uint32 v_rowoff = (uint32)((((l >> 3) & 1) * 8 + (l & 7)) * 256);
    const int ck0 = (l >> 3) & 1;
    const int cv0 = l >> 4;

    // ---- flash state ----
    float o[16][4];
    #pragma unroll
    for (int i = 0; i < 16; ++i) { o[i][0] = o[i][1] = o[i][2] = o[i][3] = 0.f; }
    float lr0 = 0.f, lr1 = 0.f;

    const int row0 = q0 + w * 16 + gid;
    const int row1 = row0 + 8;
    const int wmax = q0 + w * 16 + 15;

    // ---- prologue: compute S(0) (tile 0 always live for every warp) ----
    float s[4][4];
    #pragma unroll
    for (int i = 0; i < 4; ++i) { s[i][0] = s[i][1] = s[i][2] = s[i][3] = 0.f; }

    CP_WAIT(1);          // KV(0) landed
    __syncthreads();
    {
        const bool np1 = (16 <= wmax);
        #pragma unroll
        for (int k = 0; k < 8; ++k) {
            const uint32 ka = smb + k_rowoff + (uint32)(((ck0 + 2 * k) ^ rx) << 4);
            uint32 kh0[4], kh1[4];
            ldm_x4(kh0, ka);
            if (np1) ldm_x4(kh1, ka + 4096);
            mma_f16(s[0], qf[k], kh0[0], kh0[1]);
            mma_f16(s[1], qf[k], kh0[2], kh0[3]);
            if (np1) { mma_f16(s[2], qf[k], kh1[0], kh1[1]);
                       mma_f16(s[3], qf[k], kh1[2], kh1[3]); }
        }
    }

    int st = 0;
    for (int kt = 0; kt < nk; ++kt) {
        const int k0 = kt * BN;

        CP_WAIT(0);                  // KV(kt+1) landed (issued a full tile ago)
        __syncthreads();             // data visible; stage (st+2)%3 drained

        if (kt + 2 < nk) {           // issue KV(kt+2)
            int sp = st + 2; if (sp >= 3) sp -= 3;
            const uint32 nb = smb + (uint32)(sp * STAGE_B);
            const size_t sk = gsrc + (size_t)((kt + 2) * BN) * RSTRIDE;
            #pragma unroll
            for (int i = 0; i < 4; ++i) {
                int ch = kch0 + 4 * i;
                const uint32 doff = (uint32)(krow * 256 + ((ch ^ (krow & 7)) << 4));
                cp16(nb + doff,         g_k16 + sk + ch * 8);
                cp16(nb + BUF_V + doff, g_v16 + sk + ch * 8);
            }
            CP_COMMIT();
        }

        if (k0 <= wmax) {            // warp-uniform: tile kt live
            int sn = st + 1; if (sn >= 3) sn -= 3;
            const uint32 kvb = smb + (uint32)(st * STAGE_B);
            const uint32 kvn = smb + (uint32)(sn * STAGE_B);
            const bool np1c = (k0 + 16 <= wmax);   // current tile, cols 16-31
            const bool snl  = (k0 + 32 <= wmax);   // next tile live
            const bool np1n = (k0 + 48 <= wmax);   // next tile, cols 16-31

            // ---- softmax(tile kt): S finalized a full iteration ago ----
            // A-frag order per kk: {lo-k0, hi-k0, lo-k1, hi-k1}
            uint32 A0[4], A1[4];
            #pragma unroll
            for (int kk = 0; kk < 2; ++kk) {
                uint32* A = kk ? A1 : A0;
                #pragma unroll
                for (int h = 0; h < 2; ++h) {
                    const int nt = 2 * kk + h;
                    float p0 = 0.f, p1 = 0.f, p2 = 0.f, p3 = 0.f;
                    if (k0 + nt * 8 <= wmax) {
                        const int c0 = k0 + nt * 8 + 2 * tig;
                        p0 = (c0     <= row0) ? ex2(s[nt][0]) : 0.f;
                        p1 = (c0 + 1 <= row0) ? ex2(s[nt][1]) : 0.f;
                        p2 = (c0     <= row1) ? ex2(s[nt][2]) : 0.f;
                        p3 = (c0 + 1 <= row1) ? ex2(s[nt][3]) : 0.f;
                        lr0 += p0 + p1;
                        lr1 += p2 + p3;
                    }
                    A[2 * h]     = pk_h2(p0, p1);
                    A[2 * h + 1] = pk_h2(p2, p3);
                }
            }

            // s consumed -> becomes accumulator for S(kt+1)
            #pragma unroll
            for (int i = 0; i < 4; ++i) { s[i][0] = s[i][1] = s[i][2] = s[i][3] = 0.f; }

            // ---- interleaved: PV(kt) + S(kt+1) ----
            #pragma unroll
            for (int j = 0; j < 8; ++j) {
                uint32 kh0[4], kh1[4], v0[4], v1[4];
                if (snl) {
                    const uint32 ka = kvn + k_rowoff + (uint32)(((ck0 + 2 * j) ^ rx) << 4);
                    ldm_x4(kh0, ka);
                    if (np1n) ldm_x4(kh1, ka + 4096);
                }
                const uint32 va = kvb + BUF_V + v_rowoff
                                + (uint32)(((cv0 + 2 * j) ^ rx) << 4);
                ldm_x4_t(v0, va);
                if (np1c) ldm_x4_t(v1, va + 4096);

                if (snl) { mma_f16(s[0], qf[j], kh0[0], kh0[1]);
                           mma_f16(s[1], qf[j], kh0[2], kh0[3]); }
                mma_f16(o[2*j],   A0, v0[0], v0[1]);
                mma_f16(o[2*j+1], A0, v0[2], v0[3]);
                if (snl && np1n) { mma_f16(s[2], qf[j], kh1[0], kh1[1]);
                                   mma_f16(s[3], qf[j], kh1[2], kh1[3]); }
                if (np1c) { mma_f16(o[2*j],   A1, v1[0], v1[1]);
                            mma_f16(o[2*j+1], A1, v1[2], v1[3]); }
            }
        }

        if (++st == 3) st = 0;
    }

    // ---- epilogue ----
    lr0 += __shfl_xor_sync(0xffffffffu, lr0, 1);
    lr0 += __shfl_xor_sync(0xffffffffu, lr0, 2);
    lr1 += __shfl_xor_sync(0xffffffffu, lr1, 1);
    lr1 += __shfl_xor_sync(0xffffffffu, lr1, 2);
    const float i0 = __fdividef(1.0f, lr0);
    const float i1 = __fdividef(1.0f, lr1);

    float* o0p = Out + (size_t)row0 * RSTRIDE + boff;
    float* o1p = Out + (size_t)row1 * RSTRIDE + boff;
    #pragma unroll
    for (int nd = 0; nd < 16; ++nd) {
        const int col = nd * 8 + 2 * tig;
        *(float2*)(o0p + col) = make_float2(o[nd][0] * i0, o[nd][1] * i0);
        *(float2*)(o1p + col) = make_float2(o[nd][2] * i1, o[nd][3] * i1);
    }
}

extern "C" void kernel_launch(void* const* d_in, const int* in_sizes, int n_in,
                              void* d_out, int out_size)
{
    const float* Q = (const float*)d_in[0];
    const float* K = (const float*)d_in[1];
    const float* V = (const float*)d_in[2];
    float* O = (float*)d_out;
    (void)in_sizes; (void)n_in; (void)out_size;

    cvt_kernel<<<NELEM / 16 / 256, 256>>>((const float4*)K, (const float4*)V);

    cudaFuncSetAttribute(attn_f16_kernel,
                         cudaFuncAttributeMaxDynamicSharedMemorySize, SMEM_TOTAL);
    dim3 grid(QTILES, NB * NH);   // (32, 32)
    attn_f16_kernel<<<grid, NTHREADS, SMEM_TOTAL>>>(Q, O);
}

// round 17
// speedup vs baseline: 1.0994x; 1.0994x over previous
#include <cuda_runtime.h>
#include <cuda_fp16.h>
#include <cstdint>

// (s, b, h, d) = (2048, 2, 16, 128), fp32 in/out, causal, scale = 1/sqrt(128)
#define SLEN     2048
#define NB       2
#define NH       16
#define HD       128
#define RSTRIDE  4096            // floats between sequence rows
#define BM       64
#define BN       32
#define QTILES   (SLEN/BM)       // 32
#define NTHREADS 128
#define SCALE    0.08838834764831845f
#define LOG2E    1.4426950408889634f
#define NELEM    (SLEN*NB*NH*HD) // 8388608

typedef unsigned int uint32;

// ---- fp16 copies of K, V (same [s][b][h][d] layout) ----
__device__ __align__(256) __half g_k16[NELEM];
__device__ __align__(256) __half g_v16[NELEM];

// ---- smem: 3 KV stages x 16KB; rows 256B (128 f16), 16B chunks XOR-swizzled ----
#define STAGE_B  16384
#define BUF_V    8192            // V tile after K tile inside a stage
#define SMEM_TOTAL (3 * STAGE_B)   // 49152 -> 3 CTAs/SM
// Q (f16, pre-scaled by SCALE*log2e) staged transiently in stage 0

// ---------------- helpers ----------------
__device__ __forceinline__ uint32 smem_u32_of(const void* p) {
    uint32 a;
    asm("{ .reg .u64 t; cvta.to.shared.u64 t, %1; cvt.u32.u64 %0, t; }" : "=r"(a) : "l"(p));
    return a;
}
__device__ __forceinline__ uint32 pk_h2(float x, float y) {
    __half2 h = __floats2half2_rn(x, y);
    return *reinterpret_cast<uint32*>(&h);
}
__device__ __forceinline__ float ex2(float x) {    // exp2, single MUFU op
    float r;
    asm("ex2.approx.f32 %0, %1;" : "=f"(r) : "f"(x));
    return r;
}
__device__ __forceinline__ void ldm_x4(uint32 r[4], uint32 addr) {
    asm volatile("ldmatrix.sync.aligned.m8n8.x4.shared.b16 {%0,%1,%2,%3}, [%4];"
                 : "=r"(r[0]), "=r"(r[1]), "=r"(r[2]), "=r"(r[3]) : "r"(addr) : "memory");
}
__device__ __forceinline__ void ldm_x4_t(uint32 r[4], uint32 addr) {
    asm volatile("ldmatrix.sync.aligned.m8n8.x4.trans.shared.b16 {%0,%1,%2,%3}, [%4];"
                 : "=r"(r[0]), "=r"(r[1]), "=r"(r[2]), "=r"(r[3]) : "r"(addr) : "memory");
}
// D += A * B  (m16n8k16, f16 in, f32 accum)
__device__ __forceinline__ void mma_f16(float c[4], const uint32 a[4], uint32 b0, uint32 b1) {
    asm volatile(
        "mma.sync.aligned.m16n8k16.row.col.f32.f16.f16.f32 "
        "{%0,%1,%2,%3}, {%4,%5,%6,%7}, {%8,%9}, {%0,%1,%2,%3};"
        : "+f"(c[0]), "+f"(c[1]), "+f"(c[2]), "+f"(c[3])
        : "r"(a[0]), "r"(a[1]), "r"(a[2]), "r"(a[3]), "r"(b0), "r"(b1));
}
__device__ __forceinline__ void cp16(uint32 dst, const void* src) {
    asm volatile("cp.async.cg.shared.global [%0], [%1], 16;" :: "r"(dst), "l"(src) : "memory");
}
#define CP_COMMIT() asm volatile("cp.async.commit_group;" ::: "memory")
#define CP_WAIT(n)  asm volatile("cp.async.wait_group %0;" :: "n"(n) : "memory")

// ---------------- pre-pass: K,V fp32 -> fp16 (2 groups/thread for MLP) ----------------
__global__ void __launch_bounds__(256)
cvt_kernel(const float4* __restrict__ K, const float4* __restrict__ V)
{
    int i0 = (blockIdx.x * 256 + threadIdx.x) * 2;   // two groups of 8 elements
    float4 ka0 = K[2*i0],   kb0 = K[2*i0+1];
    float4 ka1 = K[2*i0+2], kb1 = K[2*i0+3];
    float4 va0 = V[2*i0],   vb0 = V[2*i0+1];
    float4 va1 = V[2*i0+2], vb1 = V[2*i0+3];
    ((uint4*)g_k16)[i0]   = make_uint4(pk_h2(ka0.x, ka0.y), pk_h2(ka0.z, ka0.w),
                                       pk_h2(kb0.x, kb0.y), pk_h2(kb0.z, kb0.w));
    ((uint4*)g_k16)[i0+1] = make_uint4(pk_h2(ka1.x, ka1.y), pk_h2(ka1.z, ka1.w),
                                       pk_h2(kb1.x, kb1.y), pk_h2(kb1.z, kb1.w));
    ((uint4*)g_v16)[i0]   = make_uint4(pk_h2(va0.x, va0.y), pk_h2(va0.z, va0.w),
                                       pk_h2(vb0.x, vb0.y), pk_h2(vb0.z, vb0.w));
    ((uint4*)g_v16)[i0+1] = make_uint4(pk_h2(va1.x, va1.y), pk_h2(va1.z, va1.w),
                                       pk_h2(vb1.x, vb1.y), pk_h2(vb1.z, vb1.w));
}

// ---------------- main attention kernel (R15 + reordered softmax/PV) ----------------
__global__ void __launch_bounds__(NTHREADS, 3)
attn_f16_kernel(const float* __restrict__ Q, float* __restrict__ Out)
{
    extern __shared__ char smem[];
    const uint32 smb = smem_u32_of(smem);

    const int t   = threadIdx.x;
    const int w   = t >> 5;
    const int l   = t & 31;
    const int gid = l >> 2;
    const int tig = l & 3;
    const int rx  = l & 7;

    const int qtile = (int)gridDim.x - 1 - (int)blockIdx.x;   // heavy first
    const int bh    = (int)blockIdx.y;
    const int boff  = (bh >> 4) * (NH * HD) + (bh & 15) * HD;
    const int q0    = qtile * BM;
    const int nk    = 2 * qtile + 2;

    // ---- Q: fp32 load, scale by SCALE*log2e, f16-round, stage, extract ----
    {
        const float qs = SCALE * LOG2E;
        const int qr = t >> 1;                  // 64 rows, 2 threads/row
        const float* Qr = Q + (size_t)(q0 + qr) * RSTRIDE + boff;
        #pragma unroll
        for (int i = 0; i < 8; ++i) {
            int ch = (t & 1) + 2 * i;           // 16B chunk = 8 f16
            const float* p = Qr + ch * 8;
            float4 a = *(const float4*)p;
            float4 b = *(const float4*)(p + 4);
            *(uint4*)(smem + qr * 256 + ((ch ^ (qr & 7)) << 4)) =
                make_uint4(pk_h2(a.x * qs, a.y * qs), pk_h2(a.z * qs, a.w * qs),
                           pk_h2(b.x * qs, b.y * qs), pk_h2(b.z * qs, b.w * qs));
        }
    }
    __syncthreads();

    uint32 qf[8][4];
    {
        const int qrow = w * 16 + (l & 15);
        const int cq0  = l >> 4;
        const uint32 q_row = smb + (uint32)(qrow * 256);
        #pragma unroll
        for (int k = 0; k < 8; ++k)
            ldm_x4(qf[k], q_row + (uint32)(((cq0 + 2 * k) ^ rx) << 4));
    }
    __syncthreads();   // stage0 free for KV(0)

    // KV staging slots: K rows via t>>2, 4 chunks each; V same pattern
    const int    krow = t >> 2;                 // 32 rows, 4 threads/row
    const int    kch0 = t & 3;                  // + 4*i
    const size_t gsrc = (size_t)krow * RSTRIDE + boff;

    // ---- prologue: issue KV(0)->stage0, KV(1)->stage1 ----
    #pragma unroll
    for (int tt = 0; tt < 2; ++tt) {
        const uint32 nb = smb + (uint32)(tt * STAGE_B);
        const size_t sk = gsrc + (size_t)(tt * BN) * RSTRIDE;
        #pragma unroll
        for (int i = 0; i < 4; ++i) {
            int ch = kch0 + 4 * i;
            const uint32 doff = (uint32)(krow * 256 + ((ch ^ (krow & 7)) << 4));
            cp16(nb + doff,         g_k16 + sk + ch * 8);
            cp16(nb + BUF_V + doff, g_v16 + sk + ch * 8);
        }
        CP_COMMIT();
    }

    // ---- per-lane K/V ldmatrix offsets ----
    const uint32 k_rowoff = (uint32)((((l >> 4) << 3) + (l & 7)) * 256);
    const uint32 v_rowoff = (uint32)((((l >> 3) & 1) * 8 + (l & 7)) * 256);
    const int ck0 = (l >> 3) & 1;
    const int cv0 = l >> 4;

    // ---- flash state ----
    float o[16][4];
    #pragma unroll
    for (int i = 0; i < 16; ++i) { o[i][0] = o[i][1] = o[i][2] = o[i][3] = 0.f; }
    float lr0 = 0.f, lr1 = 0.f;

    const int row0 = q0 + w * 16 + gid;
    const int row1 = row0 + 8;
    const int wmax = q0 + w * 16 + 15;

    int st = 0;
    for (int kt = 0; kt < nk; ++kt) {
        const int k0 = kt * BN;

        if (kt + 1 < nk) { CP_WAIT(1); } else { CP_WAIT(0); }
        __syncthreads();             // tile kt visible; stage for kt+2 drained

        if (kt + 2 < nk) {           // issue KV(kt+2)
            int sp = st + 2; if (sp >= 3) sp -= 3;
            const uint32 nb = smb + (uint32)(sp * STAGE_B);
            const size_t sk = gsrc + (size_t)((kt + 2) * BN) * RSTRIDE;
            #pragma unroll
            for (int i = 0; i < 4; ++i) {
                int ch = kch0 + 4 * i;
                const uint32 doff = (uint32)(krow * 256 + ((ch ^ (krow & 7)) << 4));
                cp16(nb + doff,         g_k16 + sk + ch * 8);
                cp16(nb + BUF_V + doff, g_v16 + sk + ch * 8);
            }
            CP_COMMIT();
        }

        if (k0 <= wmax) {            // warp-uniform causal skip
            const uint32 kvb = smb + (uint32)(st * STAGE_B);
            const bool np1 = (k0 + 16 <= wmax);

            // ---- S pass 1: nt 0,1 (kv cols 0-15) ----
            float s[4][4];
            s[0][0] = s[0][1] = s[0][2] = s[0][3] = 0.f;
            s[1][0] = s[1][1] = s[1][2] = s[1][3] = 0.f;
            #pragma unroll
            for (int k = 0; k < 8; ++k) {
                const uint32 ka = kvb + k_rowoff + (uint32)(((ck0 + 2 * k) ^ rx) << 4);
                uint32 kh0[4];
                ldm_x4(kh0, ka);
                mma_f16(s[0], qf[k], kh0[0], kh0[1]);
                mma_f16(s[1], qf[k], kh0[2], kh0[3]);
            }

            // ---- S pass 2: nt 2,3 (kv cols 16-31); hides pass-1 MMA latency ----
            s[2][0] = s[2][1] = s[2][2] = s[2][3] = 0.f;
            s[3][0] = s[3][1] = s[3][2] = s[3][3] = 0.f;
            if (np1) {
                #pragma unroll
                for (int k = 0; k < 8; ++k) {
                    const uint32 ka = kvb + k_rowoff + (uint32)(((ck0 + 2 * k) ^ rx) << 4);
                    uint32 kh1[4];
                    ldm_x4(kh1, ka + 4096);
                    mma_f16(s[2], qf[k], kh1[0], kh1[1]);
                    mma_f16(s[3], qf[k], kh1[2], kh1[3]);
                }
            }

            // ---- softmax kk=0 (s[0],s[1] retired long ago) ----
            // A-frag order: {lo-k0, hi-k0, lo-k1, hi-k1}
            uint32 A0[4];
            #pragma unroll
            for (int h = 0; h < 2; ++h) {
                const int nt = h;
                float p0 = 0.f, p1 = 0.f, p2 = 0.f, p3 = 0.f;
                if (k0 + nt * 8 <= wmax) {
                    const int c0 = k0 + nt * 8 + 2 * tig;
                    p0 = (c0     <= row0) ? ex2(s[nt][0]) : 0.f;
                    p1 = (c0 + 1 <= row0) ? ex2(s[nt][1]) : 0.f;
                    p2 = (c0     <= row1) ? ex2(s[nt][2]) : 0.f;
                    p3 = (c0 + 1 <= row1) ? ex2(s[nt][3]) : 0.f;
                    lr0 += p0 + p1;
                    lr1 += p2 + p3;
                }
                A0[2 * h]     = pk_h2(p0, p1);
                A0[2 * h + 1] = pk_h2(p2, p3);
            }

            // ---- PV kk=0 ----
            #pragma unroll
            for (int nd = 0; nd < 8; ++nd) {
                uint32 vh[4];
                ldm_x4_t(vh, kvb + BUF_V + v_rowoff
                             + (uint32)(((cv0 + 2 * nd) ^ rx) << 4));
                mma_f16(o[2*nd],   A0, vh[0], vh[1]);
                mma_f16(o[2*nd+1], A0, vh[2], vh[3]);
            }

            // ---- softmax kk=1 (issues while PV kk0 HMMAs drain) + PV kk=1 ----
            if (np1) {
                uint32 A1[4];
                #pragma unroll
                for (int h = 0; h < 2; ++h) {
                    const int nt = 2 + h;
                    float p0 = 0.f, p1 = 0.f, p2 = 0.f, p3 = 0.f;
                    if (k0 + nt * 8 <= wmax) {
                        const int c0 = k0 + nt * 8 + 2 * tig;
                        p0 = (c0     <= row0) ? ex2(s[nt][0]) : 0.f;
                        p1 = (c0 + 1 <= row0) ? ex2(s[nt][1]) : 0.f;
                        p2 = (c0     <= row1) ? ex2(s[nt][2]) : 0.f;
                        p3 = (c0 + 1 <= row1) ? ex2(s[nt][3]) : 0.f;
                        lr0 += p0 + p1;
                        lr1 += p2 + p3;
                    }
                    A1[2 * h]     = pk_h2(p0, p1);
                    A1[2 * h + 1] = pk_h2(p2, p3);
                }
                #pragma unroll
                for (int nd = 0; nd < 8; ++nd) {
                    uint32 vh[4];
                    ldm_x4_t(vh, kvb + BUF_V + v_rowoff + 4096u
                                 + (uint32)(((cv0 + 2 * nd) ^ rx) << 4));
                    mma_f16(o[2*nd],   A1, vh[0], vh[1]);
                    mma_f16(o[2*nd+1], A1, vh[2], vh[3]);
                }
            }
        }

        if (++st == 3) st = 0;
    }

    // ---- epilogue ----
    lr0 += __shfl_xor_sync(0xffffffffu, lr0, 1);
    lr0 += __shfl_xor_sync(0xffffffffu, lr0, 2);
    lr1 += __shfl_xor_sync(0xffffffffu, lr1, 1);
    lr1 += __shfl_xor_sync(0xffffffffu, lr1, 2);
    const float i0 = __fdividef(1.0f, lr0);
    const float i1 = __fdividef(1.0f, lr1);

    float* o0p = Out + (size_t)row0 * RSTRIDE + boff;
    float* o1p = Out + (size_t)row1 * RSTRIDE + boff;
    #pragma unroll
    for (int nd = 0; nd < 16; ++nd) {
        const int col = nd * 8 + 2 * tig;
        *(float2*)(o0p + col) = make_float2(o[nd][0] * i0, o[nd][1] * i0);
        *(float2*)(o1p + col) = make_float2(o[nd][2] * i1, o[nd][3] * i1);
    }
}

extern "C" void kernel_launch(void* const* d_in, const int* in_sizes, int n_in,
                              void* d_out, int out_size)
{
    const float* Q = (const float*)d_in[0];
    const float* K = (const float*)d_in[1];
    const float* V = (const float*)d_in[2];
    float* O = (float*)d_out;
    (void)in_sizes; (void)n_in; (void)out_size;

    cvt_kernel<<<NELEM / 16 / 256, 256>>>((const float4*)K, (const float4*)V);

    cudaFuncSetAttribute(attn_f16_kernel,
                         cudaFuncAttributeMaxDynamicSharedMemorySize, SMEM_TOTAL);
    dim3 grid(QTILES, NB * NH);   // (32, 32)
    attn_f16_kernel<<<grid, NTHREADS, SMEM_TOTAL>>>(Q, O);
}